// round 16
// baseline (speedup 1.0000x reference)
#include <cuda_runtime.h>
#include <cuda_fp16.h>
#include <cstdint>

#define NN   20000
#define EE   320000
#define BUCK 96
#define HMAX 4

// ---------------- scratch (device globals; no allocation allowed) ----------------
__device__ __half g_bufH[(size_t)NN * 256];  // h = in @ W, fp16 (gather table)
__device__ __half g_bufB[(size_t)NN * 256];  // activated aggregated output (fp16)
__device__ float  g_als[NN * HMAX];
__device__ float  g_ald[NN * HMAX];
__device__ int    g_cursor[NN];
__device__ int2   g_epack[(size_t)NN * BUCK]; // incoming edges per node (bucketed)
__device__ float  g_aeK[9];                  // 4 (L0) + 4 (L1) + 1 (L2)
__device__ int    g_is64;
__device__ unsigned g_alsmax[9];             // keyed-float per (layer,head) slot
__device__ unsigned g_evabs;                 // bits of max |eattr|

typedef unsigned long long ull;

// keyed float for atomic max over signed floats
__device__ __forceinline__ unsigned fkey(float f) {
    unsigned b = __float_as_uint(f);
    return (b & 0x80000000u) ? ~b : (b | 0x80000000u);
}
__device__ __forceinline__ float fdec(unsigned k) {
    unsigned b = (k & 0x80000000u) ? (k & 0x7fffffffu) : ~k;
    return __uint_as_float(b);
}

__device__ __forceinline__ float tf32r(float x) {
    asm("cvt.rna.tf32.f32 %0, %1;" : "=f"(x) : "f"(x));
    return x;
}

// packed f32x2 fma: acc = a * w2 + acc (lane-wise on 2 packed floats)
__device__ __forceinline__ void ffma2(ull& acc, ull a, ull w2) {
    asm("fma.rn.f32x2 %0, %1, %2, %0;" : "+l"(acc) : "l"(a), "l"(w2));
}
__device__ __forceinline__ ull packf2(float lo, float hi) {
    ull r;
    asm("mov.b64 %0, {%1, %2};" : "=l"(r) : "f"(lo), "f"(hi));
    return r;
}
__device__ __forceinline__ float2 unpackf2(ull v) {
    float lo, hi;
    asm("mov.b64 {%0, %1}, %2;" : "=f"(lo), "=f"(hi) : "l"(v));
    return make_float2(lo, hi);
}
// half2 (as uint) -> packed f32x2 in a 64-bit reg
__device__ __forceinline__ ull h2tof2(unsigned h2) {
    float2 f = __half22float2(*(__half2*)&h2);
    return packf2(f.x, f.y);
}

// ---------------- init: cursors; block 0 detects dtype; blocks 79.. compute aeK ----------------
__global__ void k_init(const int* __restrict__ ei32,
                       const float* We0, const float* ae0,
                       const float* We1, const float* ae1,
                       const float* We2, const float* ae2) {
    int i = blockIdx.x * blockDim.x + threadIdx.x;
    if (i < NN) g_cursor[i] = i * BUCK;
    if (i < 9)   g_alsmax[i] = 0u;
    if (i == 9)  g_evabs = 0u;
    if (blockIdx.x == 0) {
        __shared__ int nz[256];
        int tid = threadIdx.x;
        int c = 0;
        for (int j = tid; j < 4096; j += 256) c += (ei32[2 * j + 1] != 0);
        nz[tid] = c;
        __syncthreads();
        for (int o = 128; o; o >>= 1) {
            if (tid < o) nz[tid] += nz[tid + o];
            __syncthreads();
        }
        if (tid == 0) g_is64 = (nz[0] == 0) ? 1 : 0;
    } else if (blockIdx.x >= 79 && threadIdx.x < 32) {
        int id = blockIdx.x - 79;   // 0..8
        const float *w, *a;
        if (id < 4)      { w = We0 + id * 64;       a = ae0 + id * 64; }
        else if (id < 8) { w = We1 + (id - 4) * 64; a = ae1 + (id - 4) * 64; }
        else             { w = We2;                 a = ae2; }
        int l = threadIdx.x;
        float s = w[l] * a[l] + w[l + 32] * a[l + 32];
        #pragma unroll
        for (int o = 16; o; o >>= 1) s += __shfl_xor_sync(0xffffffffu, s, o);
        if (l == 0) g_aeK[id] = s;
    }
}

// ---------------- single-pass scatter: 2 edges per thread, 1 atomic per edge ----------------
__global__ void k_scatter(const void* __restrict__ ei, const float* __restrict__ eattr) {
    __shared__ unsigned smx;
    int tid = threadIdx.x;
    if (tid == 0) smx = 0u;
    __syncthreads();
    int e0 = (blockIdx.x * blockDim.x + tid) * 2;   // EE divisible by 512
    int s0, s1, d0, d1;
    if (g_is64) {
        longlong2 dv = *(const longlong2*)((const long long*)ei + EE + e0);
        longlong2 sv = *(const longlong2*)((const long long*)ei + e0);
        d0 = (int)dv.x; d1 = (int)dv.y; s0 = (int)sv.x; s1 = (int)sv.y;
    } else {
        int2 dv = *(const int2*)((const int*)ei + EE + e0);
        int2 sv = *(const int2*)((const int*)ei + e0);
        d0 = dv.x; d1 = dv.y; s0 = sv.x; s1 = sv.y;
    }
    d0 &= 0x7fffffff; if (d0 >= NN) d0 = 0;
    d1 &= 0x7fffffff; if (d1 >= NN) d1 = 0;
    s0 &= 0x7fffffff; if (s0 >= NN) s0 = 0;
    s1 &= 0x7fffffff; if (s1 >= NN) s1 = 0;
    float2 ev = *(const float2*)(eattr + e0);

    int p0 = atomicAdd(&g_cursor[d0], 1);
    if (p0 < (d0 + 1) * BUCK) g_epack[p0] = make_int2(s0, __float_as_int(ev.x));
    int p1 = atomicAdd(&g_cursor[d1], 1);
    if (p1 < (d1 + 1) * BUCK) g_epack[p1] = make_int2(s1, __float_as_int(ev.y));

    atomicMax(&smx, __float_as_uint(fmaxf(fabsf(ev.x), fabsf(ev.y))));
    __syncthreads();
    if (tid == 0) atomicMax(&g_evabs, smx);
}

// ---------------- tf32 TC GEMM + fused attention dots ----------------
// SRCSEL: 0 = external fp32 A, 2 = g_bufB (fp16; half->tf32 is exact).
template<int SRCSEL, int KTILE>
__global__ void __launch_bounds__(256) k_gemm_tc(const float* __restrict__ Aext,
                                                 const float* __restrict__ B,
                                                 const float* __restrict__ a_srcw,
                                                 const float* __restrict__ a_dstw,
                                                 int slot, int M, int K, int N) {
    __shared__ float As[128][KTILE + 4];
    __shared__ float Bs[KTILE][72];
    __shared__ float sAttn[128];
    __shared__ float sPS[128][2], sPD[128][2];
    __shared__ unsigned smaxsh;
    const int bm = blockIdx.x * 128;
    const int bn = blockIdx.y * 64;
    const int head = blockIdx.y;
    const int Hh = gridDim.y;
    const int tid = threadIdx.x;
    const int wid = tid >> 5;
    const int lane = tid & 31;
    const int grp = lane >> 2;
    const int q = lane & 3;
    const int wm = (wid >> 1) * 32;
    const int wn = (wid & 1) * 32;

    if (tid < 64)       sAttn[tid] = a_srcw[head * 64 + tid];
    else if (tid < 128) sAttn[tid] = a_dstw[head * 64 + (tid - 64)];
    if (tid == 128) smaxsh = 0u;

    float c[2][4][4];
    #pragma unroll
    for (int mi = 0; mi < 2; mi++)
        #pragma unroll
        for (int ni = 0; ni < 4; ni++)
            #pragma unroll
            for (int j = 0; j < 4; j++) c[mi][ni][j] = 0.f;

    for (int k0 = 0; k0 < K; k0 += KTILE) {
        // fill A
        #pragma unroll
        for (int it = 0; it < 128 * (KTILE / 4) / 256; it++) {
            int linear = tid + it * 256;
            int r = linear / (KTILE / 4);
            int cg = linear % (KTILE / 4);
            float4 v = make_float4(0.f, 0.f, 0.f, 0.f);
            if (bm + r < M) {
                if (SRCSEL == 0) {
                    v = *(const float4*)(Aext + (size_t)(bm + r) * K + k0 + 4 * cg);
                } else {
                    uint2 hv = *(const uint2*)((const __half*)g_bufB + (size_t)(bm + r) * K + k0 + 4 * cg);
                    float2 f0 = __half22float2(*(__half2*)&hv.x);
                    float2 f1 = __half22float2(*(__half2*)&hv.y);
                    v = make_float4(f0.x, f0.y, f1.x, f1.y);
                }
            }
            *(float4*)&As[r][4 * cg] = make_float4(tf32r(v.x), tf32r(v.y), tf32r(v.z), tf32r(v.w));
        }
        // fill B
        #pragma unroll
        for (int it = 0; it < KTILE * 16 / 256; it++) {
            int linear = tid + it * 256;
            int k = linear >> 4;
            int cg = linear & 15;
            float4 v = *(const float4*)(B + (size_t)(k0 + k) * N + bn + 4 * cg);
            *(float4*)&Bs[k][4 * cg] = make_float4(tf32r(v.x), tf32r(v.y), tf32r(v.z), tf32r(v.w));
        }
        __syncthreads();

        #pragma unroll
        for (int kk = 0; kk < KTILE; kk += 8) {
            unsigned a[2][4], b[4][2];
            #pragma unroll
            for (int mi = 0; mi < 2; mi++) {
                int r0 = wm + mi * 16 + grp;
                a[mi][0] = __float_as_uint(As[r0][kk + q]);
                a[mi][1] = __float_as_uint(As[r0 + 8][kk + q]);
                a[mi][2] = __float_as_uint(As[r0][kk + q + 4]);
                a[mi][3] = __float_as_uint(As[r0 + 8][kk + q + 4]);
            }
            #pragma unroll
            for (int ni = 0; ni < 4; ni++) {
                int cn = wn + ni * 8 + grp;
                b[ni][0] = __float_as_uint(Bs[kk + q][cn]);
                b[ni][1] = __float_as_uint(Bs[kk + q + 4][cn]);
            }
            #pragma unroll
            for (int mi = 0; mi < 2; mi++)
                #pragma unroll
                for (int ni = 0; ni < 4; ni++) {
                    asm volatile(
                        "mma.sync.aligned.m16n8k8.row.col.f32.tf32.tf32.f32 "
                        "{%0,%1,%2,%3}, {%4,%5,%6,%7}, {%8,%9}, {%0,%1,%2,%3};"
                        : "+f"(c[mi][ni][0]), "+f"(c[mi][ni][1]),
                          "+f"(c[mi][ni][2]), "+f"(c[mi][ni][3])
                        : "r"(a[mi][0]), "r"(a[mi][1]), "r"(a[mi][2]), "r"(a[mi][3]),
                          "r"(b[ni][0]), "r"(b[ni][1]));
                }
        }
        __syncthreads();
    }

    // ---- store h (fp16) ----
    #pragma unroll
    for (int mi = 0; mi < 2; mi++) {
        #pragma unroll
        for (int ni = 0; ni < 4; ni++) {
            int col = bn + wn + ni * 8 + 2 * q;
            int r0 = bm + wm + mi * 16 + grp;
            if (r0 < M)
                *(__half2*)((__half*)g_bufH + (size_t)r0 * N + col) =
                    __floats2half2_rn(c[mi][ni][0], c[mi][ni][1]);
            if (r0 + 8 < M)
                *(__half2*)((__half*)g_bufH + (size_t)(r0 + 8) * N + col) =
                    __floats2half2_rn(c[mi][ni][2], c[mi][ni][3]);
        }
    }

    // ---- fused attention dots ----
    float ds[4] = {0.f, 0.f, 0.f, 0.f}, dd[4] = {0.f, 0.f, 0.f, 0.f};
    #pragma unroll
    for (int mi = 0; mi < 2; mi++)
        #pragma unroll
        for (int ni = 0; ni < 4; ni++) {
            int cb = wn + ni * 8 + 2 * q;
            float as0 = sAttn[cb], as1 = sAttn[cb + 1];
            float ad0 = sAttn[64 + cb], ad1 = sAttn[64 + cb + 1];
            ds[mi * 2 + 0] += c[mi][ni][0] * as0 + c[mi][ni][1] * as1;
            dd[mi * 2 + 0] += c[mi][ni][0] * ad0 + c[mi][ni][1] * ad1;
            ds[mi * 2 + 1] += c[mi][ni][2] * as0 + c[mi][ni][3] * as1;
            dd[mi * 2 + 1] += c[mi][ni][2] * ad0 + c[mi][ni][3] * ad1;
        }
    #pragma unroll
    for (int r = 0; r < 4; r++) {
        ds[r] += __shfl_xor_sync(0xffffffffu, ds[r], 1);
        ds[r] += __shfl_xor_sync(0xffffffffu, ds[r], 2);
        dd[r] += __shfl_xor_sync(0xffffffffu, dd[r], 1);
        dd[r] += __shfl_xor_sync(0xffffffffu, dd[r], 2);
    }
    if (q == 0) {
        int nw = wid & 1;
        #pragma unroll
        for (int r = 0; r < 4; r++) {
            int row = wm + r * 8 + grp;
            sPS[row][nw] = ds[r];
            sPD[row][nw] = dd[r];
        }
    }
    __syncthreads();
    if (tid < 128) {
        int grow = bm + tid;
        if (grow < M) {
            float s = sPS[tid][0] + sPS[tid][1];
            float d = sPD[tid][0] + sPD[tid][1];
            g_als[(size_t)grow * Hh + head] = s;
            g_ald[(size_t)grow * Hh + head] = d;
            atomicMax(&smaxsh, fkey(s));
        }
    }
    __syncthreads();
    if (tid == 0) atomicMax(&g_alsmax[slot + head], smaxsh);
}

// ---------------- H=4 aggregation: two-phase dedup; lane = (head, part) ----------------
__global__ void k_agg4(const float* __restrict__ bias, int aekBase) {
    int gw = (blockIdx.x * blockDim.x + threadIdx.x) >> 5;
    int lane = threadIdx.x & 31;
    if (gw >= NN) return;
    int n = gw;
    int beg = n * BUCK, end = g_cursor[n];
    int deg = end - beg;
    const __half* __restrict__ h = (const __half*)g_bufH;
    const float evab = __uint_as_float(g_evabs);
    const int head = lane >> 3;       // 0..3
    const int part = lane & 7;        // 0..7
    const int lbase = lane & 24;      // head*8
    const int c0 = head * 64 + part * 8;

    float aek = g_aeK[aekBase + head];
    float ald = g_ald[n * 4 + head];
    float zb = fdec(g_alsmax[aekBase + head]) + ald + fabsf(aek) * evab;
    float m = (zb > 0.f) ? zb : 0.2f * zb;
    float denp = 0.f, evp = 0.f;      // per-lane partials (reduced over 8-lane group)
    ull acc[4] = {0ull, 0ull, 0ull, 0ull};

    int base = beg;
    // full chunks of 8 edges
    for (; base + 8 <= end; base += 8) {
        // phase 1: lane handles edge base+part under its own head
        int2 ep = g_epack[base + part];
        int s_mine = ep.x;
        float ev = __int_as_float(ep.y);
        evp += ev;
        float a = g_als[s_mine * 4 + head] + ald + ev * aek;
        a = (a > 0.f) ? a : 0.2f * a;
        float w_mine = __expf(a - m);
        denp += w_mine;
        // phase 2: broadcast (s, w) within head group, gather + accumulate
        #pragma unroll
        for (int e = 0; e < 8; e++) {
            int s   = __shfl_sync(0xffffffffu, s_mine, lbase + e);
            float w = __shfl_sync(0xffffffffu, w_mine, lbase + e);
            ull w2 = packf2(w, w);
            uint4 hv = *(const uint4*)(h + (size_t)s * 256 + c0);
            ffma2(acc[0], h2tof2(hv.x), w2);
            ffma2(acc[1], h2tof2(hv.y), w2);
            ffma2(acc[2], h2tof2(hv.z), w2);
            ffma2(acc[3], h2tof2(hv.w), w2);
        }
    }
    // tail chunk
    if (base < end) {
        int rem = end - base;
        int s_mine = 0;
        float w_mine = 0.f;
        if (part < rem) {
            int2 ep = g_epack[base + part];
            s_mine = ep.x;
            float ev = __int_as_float(ep.y);
            evp += ev;
            float a = g_als[s_mine * 4 + head] + ald + ev * aek;
            a = (a > 0.f) ? a : 0.2f * a;
            w_mine = __expf(a - m);
            denp += w_mine;
        }
        #pragma unroll 2
        for (int e = 0; e < rem; e++) {
            int s   = __shfl_sync(0xffffffffu, s_mine, lbase + e);
            float w = __shfl_sync(0xffffffffu, w_mine, lbase + e);
            ull w2 = packf2(w, w);
            uint4 hv = *(const uint4*)(h + (size_t)s * 256 + c0);
            ffma2(acc[0], h2tof2(hv.x), w2);
            ffma2(acc[1], h2tof2(hv.y), w2);
            ffma2(acc[2], h2tof2(hv.z), w2);
            ffma2(acc[3], h2tof2(hv.w), w2);
        }
    }
    // reduce den / evsum over the 8-lane head group
    #pragma unroll
    for (int o = 4; o; o >>= 1) {
        denp += __shfl_xor_sync(0xffffffffu, denp, o);
        evp  += __shfl_xor_sync(0xffffffffu, evp, o);
    }
    // self loop: eval = mean of incoming evals (0 if none)
    {
        float mean_ev = evp / fmaxf((float)deg, 1.f);
        float a = g_als[n * 4 + head] + ald + mean_ev * aek;
        a = (a > 0.f) ? a : 0.2f * a;
        float w = __expf(a - m);
        denp += w;
        ull w2 = packf2(w, w);
        uint4 hv = *(const uint4*)(h + (size_t)n * 256 + c0);
        ffma2(acc[0], h2tof2(hv.x), w2);
        ffma2(acc[1], h2tof2(hv.y), w2);
        ffma2(acc[2], h2tof2(hv.z), w2);
        ffma2(acc[3], h2tof2(hv.w), w2);
    }
    float inv = 1.f / (denp + 1e-16f);
    __half2 o[4];
    #pragma unroll
    for (int j = 0; j < 4; j++) {
        float2 f = unpackf2(acc[j]);
        float v0 = f.x * inv + bias[c0 + 2 * j];
        float v1 = f.y * inv + bias[c0 + 2 * j + 1];
        v0 = (v0 > 0.f) ? v0 : (__expf(v0) - 1.f);
        v1 = (v1 > 0.f) ? v1 : (__expf(v1) - 1.f);
        o[j] = __floats2half2_rn(v0, v1);
    }
    *(uint4*)((__half*)g_bufB + (size_t)n * 256 + c0) = *(uint4*)o;
}

// ---------------- H=1 final aggregation (two-phase dedup) + LayerNorm -> outp ----------------
__global__ void k_agg1(const float* __restrict__ bias,
                       float* __restrict__ outp,
                       int aekBase,
                       const float* __restrict__ lng,
                       const float* __restrict__ lnb) {
    int gw = (blockIdx.x * blockDim.x + threadIdx.x) >> 5;
    int lane = threadIdx.x & 31;
    if (gw >= NN) return;
    int n = gw;
    int beg = n * BUCK, end = g_cursor[n];
    int deg = end - beg;
    const __half* __restrict__ h = (const __half*)g_bufH;
    const float evab = __uint_as_float(g_evabs);

    float aek = g_aeK[aekBase];
    float ald = g_ald[n];
    float zb = fdec(g_alsmax[aekBase]) + ald + fabsf(aek) * evab;
    float m = (zb > 0.f) ? zb : 0.2f * zb;
    float denp = 0.f, evp = 0.f;
    ull acc = 0ull;
    const int c0 = 2 * lane;

    for (int base = beg; base < end; base += 32) {
        int rem = end - base;
        int cnt = rem < 32 ? rem : 32;
        int s_mine = 0;
        float w_mine = 0.f;
        if (lane < cnt) {
            int2 ep = g_epack[base + lane];
            s_mine = ep.x;
            float ev = __int_as_float(ep.y);
            evp += ev;
            float a = g_als[s_mine] + ald + ev * aek;
            a = (a > 0.f) ? a : 0.2f * a;
            w_mine = __expf(a - m);
            denp += w_mine;
        }
        #pragma unroll 4
        for (int e = 0; e < cnt; e++) {
            int s   = __shfl_sync(0xffffffffu, s_mine, e);
            float w = __shfl_sync(0xffffffffu, w_mine, e);
            unsigned hv = *(const unsigned*)(h + (size_t)s * 64 + c0);
            ffma2(acc, h2tof2(hv), packf2(w, w));
        }
    }
    #pragma unroll
    for (int o = 16; o; o >>= 1) {
        denp += __shfl_xor_sync(0xffffffffu, denp, o);
        evp  += __shfl_xor_sync(0xffffffffu, evp, o);
    }
    {
        float mean_ev = evp / fmaxf((float)deg, 1.f);
        float a = g_als[n] + ald + mean_ev * aek;
        a = (a > 0.f) ? a : 0.2f * a;
        float w = __expf(a - m);
        denp += w;
        unsigned hv = *(const unsigned*)(h + (size_t)n * 64 + c0);
        ffma2(acc, h2tof2(hv), packf2(w, w));
    }
    float inv = 1.f / (denp + 1e-16f);
    float2 f = unpackf2(acc);
    float vx = f.x * inv + bias[c0];
    float vy = f.y * inv + bias[c0 + 1];
    float s1 = vx + vy, s2 = vx * vx + vy * vy;
    #pragma unroll
    for (int o = 16; o; o >>= 1) {
        s1 += __shfl_xor_sync(0xffffffffu, s1, o);
        s2 += __shfl_xor_sync(0xffffffffu, s2, o);
    }
    float mu = s1 * (1.f / 64.f);
    float var = s2 * (1.f / 64.f) - mu * mu;
    float rstd = rsqrtf(var + 1e-5f);
    outp[(size_t)n * 64 + c0]     = (vx - mu) * rstd * lng[c0]     + lnb[c0];
    outp[(size_t)n * 64 + c0 + 1] = (vy - mu) * rstd * lng[c0 + 1] + lnb[c0 + 1];
}

// ---------------- launch ----------------
extern "C" void kernel_launch(void* const* d_in, const int* in_sizes, int n_in,
                              void* d_out, int out_size) {
    const float* x     = (const float*)d_in[0];
    const void*  ei    = d_in[1];
    const float* eattr = (const float*)d_in[2];
    const float* W0  = (const float*)d_in[3];
    const float* as0 = (const float*)d_in[4];
    const float* ad0 = (const float*)d_in[5];
    const float* We0 = (const float*)d_in[6];
    const float* ae0 = (const float*)d_in[7];
    const float* b0  = (const float*)d_in[8];
    const float* W1  = (const float*)d_in[9];
    const float* as1 = (const float*)d_in[10];
    const float* ad1 = (const float*)d_in[11];
    const float* We1 = (const float*)d_in[12];
    const float* ae1 = (const float*)d_in[13];
    const float* b1  = (const float*)d_in[14];
    const float* W2  = (const float*)d_in[15];
    const float* as2 = (const float*)d_in[16];
    const float* ad2 = (const float*)d_in[17];
    const float* We2 = (const float*)d_in[18];
    const float* ae2 = (const float*)d_in[19];
    const float* b2  = (const float*)d_in[20];
    const float* lng = (const float*)d_in[21];
    const float* lnb = (const float*)d_in[22];
    float* outp = (float*)d_out;

    // ---- graph prep (stateless; bucketed, single edge pass) ----
    k_init<<<79 + 9, 256>>>((const int*)ei, We0, ae0, We1, ae1, We2, ae2);
    k_scatter<<<EE / 512, 256>>>(ei, eattr);

    const int aggB = (NN * 32 + 255) / 256;
    const int gx = (NN + 127) / 128;

    // ---- layer 0 ----
    {
        dim3 g(gx, 4);
        k_gemm_tc<0, 16><<<g, 256>>>(x, W0, as0, ad0, 0, NN, 16, 256);
        k_agg4<<<aggB, 256>>>(b0, 0);
    }
    // ---- layer 1 ----
    {
        dim3 g(gx, 4);
        k_gemm_tc<2, 32><<<g, 256>>>(nullptr, W1, as1, ad1, 4, NN, 256, 256);
        k_agg4<<<aggB, 256>>>(b1, 4);
    }
    // ---- layer 2 ----
    {
        dim3 g(gx, 1);
        k_gemm_tc<2, 32><<<g, 256>>>(nullptr, W2, as2, ad2, 8, NN, 256, 64);
        k_agg1<<<aggB, 256>>>(b2, outp, 8, lng, lnb);
    }
}